// round 11
// baseline (speedup 1.0000x reference)
#include <cuda_runtime.h>
#include <cuda_fp16.h>
#include <cstdint>

#define B_DIM  8192
#define IN_DIM 1024
#define H_DIM  1024
#define KTOT   2048
#define N4H    4096
#define BH     (B_DIM * H_DIM)

// ---------------- device scratch (static globals: allocation-free) ----------
__device__ __align__(1024) __half g_A[(size_t)B_DIM * KTOT];   // [8192,2048] fp16  [x | h]
__device__ __align__(1024) __half g_W[(size_t)N4H * KTOT];     // [4096,2048] fp16, row = 4*h+gate
__device__ __align__(1024) float  g_bias[N4H];                 // interleaved 4*h+gate (i,f,g,o)

// ---------------- PTX helpers ----------------------------------------------
__device__ __forceinline__ uint32_t smem_u32(const void* p) {
    uint32_t a;
    asm("{ .reg .u64 t; cvta.to.shared.u64 t, %1; cvt.u32.u64 %0, t; }" : "=r"(a) : "l"(p));
    return a;
}
#define CP16(sm, gp) \
    asm volatile("cp.async.cg.shared.global [%0], [%1], 16;" :: "r"(sm), "l"(gp) : "memory")
#define CP_COMMIT() asm volatile("cp.async.commit_group;" ::: "memory")
#define CP_WAIT(n)  asm volatile("cp.async.wait_group %0;" :: "n"(n) : "memory")

// named barriers: producer/consumer handshake (320 threads total)
#define BAR_SYNC(id)   asm volatile("bar.sync %0, 320;"   :: "r"(id) : "memory")
#define BAR_ARRIVE(id) asm volatile("bar.arrive %0, 320;" :: "r"(id) : "memory")

#define LDSM_X4(r, addr)                                                        \
    asm volatile("ldmatrix.sync.aligned.m8n8.x4.shared.b16 {%0,%1,%2,%3}, [%4];" \
        : "=r"((r)[0]), "=r"((r)[1]), "=r"((r)[2]), "=r"((r)[3]) : "r"(addr))

#define MMA16816(c, a, b0, b1)                                                  \
    asm volatile("mma.sync.aligned.m16n8k16.row.col.f32.f16.f16.f32 "           \
        "{%0,%1,%2,%3}, {%4,%5,%6,%7}, {%8,%9}, {%0,%1,%2,%3};"                 \
        : "+f"((c)[0]), "+f"((c)[1]), "+f"((c)[2]), "+f"((c)[3])                \
        : "r"((a)[0]), "r"((a)[1]), "r"((a)[2]), "r"((a)[3]), "r"(b0), "r"(b1))

__device__ __forceinline__ float sigf(float x) { return 1.f / (1.f + __expf(-x)); }
__device__ __forceinline__ float tanhf_(float x) {
    float t = __expf(-2.f * x);
    return (1.f - t) * (1.f / (1.f + t));
}

// ---------------- pack kernels ---------------------------------------------
__global__ void __launch_bounds__(256) pack_A(const float* __restrict__ x,
                                              const float* __restrict__ h) {
    int i = blockIdx.x * 256 + threadIdx.x;
    int b = i >> 8;
    int k = (i & 255) << 2;
    float4 vx = *reinterpret_cast<const float4*>(x + (size_t)b * IN_DIM + k);
    float4 vh = *reinterpret_cast<const float4*>(h + (size_t)b * H_DIM + k);
    __half2* dx = reinterpret_cast<__half2*>(g_A + (size_t)b * KTOT + k);
    dx[0] = __floats2half2_rn(vx.x, vx.y);
    dx[1] = __floats2half2_rn(vx.z, vx.w);
    __half2* dh = reinterpret_cast<__half2*>(g_A + (size_t)b * KTOT + IN_DIM + k);
    dh[0] = __floats2half2_rn(vh.x, vh.y);
    dh[1] = __floats2half2_rn(vh.z, vh.w);
}

__global__ void __launch_bounds__(256) pack_W(
    const float* __restrict__ Wix, const float* __restrict__ Wfx,
    const float* __restrict__ Wgx, const float* __restrict__ Wox,
    const float* __restrict__ Wih, const float* __restrict__ Wfh,
    const float* __restrict__ Wgh, const float* __restrict__ Woh) {
    int i = blockIdx.x * 256 + threadIdx.x;
    int n = i >> 9;
    int k = (i & 511) << 2;
    int r = n >> 2;
    int g = n & 3;
    const float* src;
    if (k < IN_DIM) {
        const float* w = (g == 0) ? Wix : (g == 1) ? Wfx : (g == 2) ? Wgx : Wox;
        src = w + (size_t)r * IN_DIM + k;
    } else {
        const float* w = (g == 0) ? Wih : (g == 1) ? Wfh : (g == 2) ? Wgh : Woh;
        src = w + (size_t)r * H_DIM + (k - IN_DIM);
    }
    float4 v = *reinterpret_cast<const float4*>(src);
    __half2* d = reinterpret_cast<__half2*>(g_W + (size_t)n * KTOT + k);
    d[0] = __floats2half2_rn(v.x, v.y);
    d[1] = __floats2half2_rn(v.z, v.w);
}

__global__ void __launch_bounds__(256) pack_bias(
    const float* __restrict__ bi, const float* __restrict__ bf,
    const float* __restrict__ bg, const float* __restrict__ bo) {
    int i = blockIdx.x * 256 + threadIdx.x;
    int r = i >> 2;
    int g = i & 3;
    const float* b = (g == 0) ? bi : (g == 1) ? bf : (g == 2) ? bg : bo;
    g_bias[i] = b[r];
}

// ---------------- warp-specialized GEMM + fused LSTM epilogue ---------------
// CTA: 320 threads = 8 consumer warps (tile 128x128, warp 32x64) + 2 producer
// warps (all cp.async). 5-stage ring, named-barrier FULL/EMPTY handshake.
// Consumers never execute cp.async nor CTA-wide syncs in the mainloop.
static constexpr int STAGES   = 5;
static constexpr int ROW_B    = 80;                    // 32 halves + pad
static constexpr int A_BYTES  = 128 * ROW_B;           // 10240
static constexpr int STAGE_B  = 2 * A_BYTES;           // 20480
static constexpr int SMEM_DYN = STAGES * STAGE_B;      // 102400
static constexpr int KITERS   = KTOT / 32;             // 64
// named barrier ids: FULL[s] = 1+s (1..5), EMPTY[s] = 6+s (6..10)

__global__ void __launch_bounds__(320, 1) lstm_gemm(
    const float* __restrict__ c_prev, float* __restrict__ out) {
    extern __shared__ __align__(128) char smem[];
    const uint32_t sbase = smem_u32(smem);

    const int tid = threadIdx.x;
    const int l   = tid & 31;
    const int wid = tid >> 5;          // 0..9
    const int bn  = blockIdx.x;        // 0..31
    const int bm  = blockIdx.y;        // 0..63

    if (wid < 8) {
        // ===================== CONSUMER WARPS =====================
        const int wm = wid >> 1;       // 0..3 : 32-row slice
        const int wn = wid & 1;        // 0..1 : 64-packed-col slice

        const uint32_t laA = sbase + (uint32_t)(wm * 32 + (l & 7) + 8 * ((l >> 3) & 1)) * ROW_B
                           + (uint32_t)(l >> 4) * 16;
        const uint32_t laB = sbase + A_BYTES
                           + (uint32_t)(wn * 64 + (l & 7) + 8 * (l >> 4)) * ROW_B
                           + (uint32_t)((l >> 3) & 1) * 16;

        float acc[2][8][4];
#pragma unroll
        for (int mb = 0; mb < 2; mb++)
#pragma unroll
            for (int nb = 0; nb < 8; nb++)
#pragma unroll
                for (int q = 0; q < 4; q++) acc[mb][nb][q] = 0.f;

        int slot = 0;
        for (int i = 0; i < KITERS; i++) {
            BAR_SYNC(1 + slot);                       // wait stage FULL
            const uint32_t so = (uint32_t)slot * STAGE_B;
#pragma unroll
            for (int ks = 0; ks < 2; ks++) {
                uint32_t af[2][4], bf[4][4];
                uint32_t ao = laA + so + ks * 32;
                uint32_t bo = laB + so + ks * 32;
#pragma unroll
                for (int mb = 0; mb < 2; mb++) LDSM_X4(af[mb], ao + mb * 16 * ROW_B);
#pragma unroll
                for (int p = 0; p < 4; p++) LDSM_X4(bf[p], bo + p * 16 * ROW_B);
#pragma unroll
                for (int mb = 0; mb < 2; mb++)
#pragma unroll
                    for (int p = 0; p < 4; p++) {
                        MMA16816(acc[mb][2 * p],     af[mb], bf[p][0], bf[p][1]);
                        MMA16816(acc[mb][2 * p + 1], af[mb], bf[p][2], bf[p][3]);
                    }
            }
            BAR_ARRIVE(6 + slot);                     // release stage EMPTY
            slot = (slot == STAGES - 1) ? 0 : slot + 1;
        }

        __syncthreads();   // ring smem now free for epilogue staging

        // ---- stage c_prev tile [128 x 32] into smem (coalesced), stride 34
        float* sh_c = reinterpret_cast<float*>(smem);
        float* sh_h = sh_c + 128 * 34;
        float* sh_n = sh_h + 128 * 34;
#pragma unroll
        for (int it = 0; it < 8; it++) {
            int idx = it * 256 + tid;                 // 0..2047 float2 slots
            int row = idx >> 4, seg = idx & 15;
            float2 v = *reinterpret_cast<const float2*>(
                c_prev + (size_t)(bm * 128 + row) * H_DIM + bn * 32 + seg * 2);
            *reinterpret_cast<float2*>(sh_c + row * 34 + seg * 2) = v;
        }
        __syncthreads();

        // ---- fused LSTM epilogue (gate-interleaved cols i,f,g,o)
        const int q = l & 3;
#pragma unroll
        for (int mb = 0; mb < 2; mb++) {
#pragma unroll
            for (int nb = 0; nb < 8; nb++) {
                int colbase = bn * 128 + wn * 64 + nb * 8;
                float2 bb = *reinterpret_cast<const float2*>(g_bias + colbase + 2 * q);
                float a0 = acc[mb][nb][0] + bb.x;
                float a1 = acc[mb][nb][1] + bb.y;
                float a2 = acc[mb][nb][2] + bb.x;
                float a3 = acc[mb][nb][3] + bb.y;
                float r0 = __shfl_xor_sync(0xFFFFFFFFu, a0, 1);
                float r1 = __shfl_xor_sync(0xFFFFFFFFu, a1, 1);
                float r2 = __shfl_xor_sync(0xFFFFFFFFu, a2, 1);
                float r3 = __shfl_xor_sync(0xFFFFFFFFu, a3, 1);
                bool ev = (l & 1) == 0;
                float zi = ev ? a0 : r2;
                float zf = ev ? a1 : r3;
                float zg = ev ? r0 : a2;
                float zo = ev ? r1 : a3;
                int rl   = wm * 32 + mb * 16 + ((l >> 2) & 7) + (l & 1) * 8;
                int hcol = wn * 16 + nb * 2 + ((l >> 1) & 1);
                float cp = sh_c[rl * 34 + hcol];
                float gi = sigf(zi), gf = sigf(zf);
                float gg = tanhf_(zg), go = sigf(zo);
                float cn = gf * cp + gi * gg;
                float hn = go * tanhf_(cn);
                sh_h[rl * 34 + hcol] = hn;
                sh_n[rl * 34 + hcol] = cn;
            }
        }
        __syncthreads();

        // ---- coalesced stores
        float* oh = out + (size_t)(bm * 128) * H_DIM + bn * 32;
        float* oc = oh + (size_t)BH;
#pragma unroll
        for (int it = 0; it < 8; it++) {
            int idx = it * 256 + tid;
            int row = idx >> 4, seg = idx & 15;
            float2 vh = *reinterpret_cast<const float2*>(sh_h + row * 34 + seg * 2);
            float2 vc = *reinterpret_cast<const float2*>(sh_n + row * 34 + seg * 2);
            *reinterpret_cast<float2*>(oh + (size_t)row * H_DIM + seg * 2) = vh;
            *reinterpret_cast<float2*>(oc + (size_t)row * H_DIM + seg * 2) = vc;
        }
    } else {
        // ===================== PRODUCER WARPS =====================
        const int ptid = tid - 256;    // 0..63
        int slot = 0;
        for (int i = 0; i < KITERS; i++) {
            if (i >= STAGES) BAR_SYNC(6 + slot);      // wait stage EMPTY
            // issue stage i into slot: A then B, 8 chunks each per thread
            {
                const uint32_t sa  = sbase + (uint32_t)slot * STAGE_B;
                const uint32_t sb2 = sa + A_BYTES;
                const __half* ga = g_A + (size_t)bm * 128 * KTOT + i * 32;
                const __half* gb = g_W + (size_t)bn * 128 * KTOT + i * 32;
#pragma unroll
                for (int j = 0; j < 8; j++) {
                    int c  = ptid + 64 * j;           // 0..511
                    int row = c >> 2, ch = c & 3;
                    CP16(sa + row * ROW_B + ch * 16,
                         ga + (size_t)row * KTOT + ch * 8);
                }
#pragma unroll
                for (int j = 0; j < 8; j++) {
                    int c  = ptid + 64 * j;
                    int row = c >> 2, ch = c & 3;
                    CP16(sb2 + row * ROW_B + ch * 16,
                         gb + (size_t)row * KTOT + ch * 8);
                }
            }
            CP_COMMIT();
            if (i >= STAGES - 1) {                    // stage i-(STAGES-1) landed
                CP_WAIT(STAGES - 1);
                int done = i - (STAGES - 1);
                BAR_ARRIVE(1 + (done % STAGES));
            }
            slot = (slot == STAGES - 1) ? 0 : slot + 1;
        }
        // drain: signal remaining stages KITERS-4 .. KITERS-1
        CP_WAIT(3); BAR_ARRIVE(1 + ((KITERS - 4) % STAGES));
        CP_WAIT(2); BAR_ARRIVE(1 + ((KITERS - 3) % STAGES));
        CP_WAIT(1); BAR_ARRIVE(1 + ((KITERS - 2) % STAGES));
        CP_WAIT(0); BAR_ARRIVE(1 + ((KITERS - 1) % STAGES));

        // join consumers for epilogue's CTA-wide syncs
        __syncthreads();
        __syncthreads();
        __syncthreads();
    }
}

// ---------------- host side -------------------------------------------------
extern "C" void kernel_launch(void* const* d_in, const int* in_sizes, int n_in,
                              void* d_out, int out_size) {
    const float* x   = (const float*)d_in[0];
    const float* h   = (const float*)d_in[1];
    const float* cp  = (const float*)d_in[2];
    const float* Wfx = (const float*)d_in[3];
    const float* bf  = (const float*)d_in[4];
    const float* Wfh = (const float*)d_in[5];
    const float* Wix = (const float*)d_in[6];
    const float* bi  = (const float*)d_in[7];
    const float* Wih = (const float*)d_in[8];
    const float* Wgx = (const float*)d_in[9];
    const float* bg  = (const float*)d_in[10];
    const float* Wgh = (const float*)d_in[11];
    const float* Wox = (const float*)d_in[12];
    const float* bo  = (const float*)d_in[13];
    const float* Woh = (const float*)d_in[14];

    pack_A<<<8192, 256>>>(x, h);
    pack_W<<<8192, 256>>>(Wix, Wfx, Wgx, Wox, Wih, Wfh, Wgh, Woh);
    pack_bias<<<16, 256>>>(bi, bf, bg, bo);

    static bool attr_set = false;
    if (!attr_set) {
        cudaFuncSetAttribute(lstm_gemm, cudaFuncAttributeMaxDynamicSharedMemorySize, SMEM_DYN);
        attr_set = true;
    }
    lstm_gemm<<<dim3(N4H / 128, B_DIM / 128), 320, SMEM_DYN>>>(cp, (float*)d_out);
}

// round 13
// speedup vs baseline: 1.2467x; 1.2467x over previous
#include <cuda_runtime.h>
#include <cuda_fp16.h>
#include <cstdint>

#define B_DIM  8192
#define IN_DIM 1024
#define H_DIM  1024
#define KTOT   2048
#define N4H    4096
#define BH     (B_DIM * H_DIM)

// ---------------- device scratch (static globals: allocation-free) ----------
__device__ __align__(1024) __half g_A[(size_t)B_DIM * KTOT];   // [8192,2048] fp16  [x | h]
__device__ __align__(1024) __half g_W[(size_t)N4H * KTOT];     // [4096,2048] fp16, row = 4*h+gate
__device__ __align__(1024) float  g_bias[N4H];                 // interleaved 4*h+gate (i,f,g,o)

// ---------------- PTX helpers ----------------------------------------------
__device__ __forceinline__ uint32_t smem_u32(const void* p) {
    uint32_t a;
    asm("{ .reg .u64 t; cvta.to.shared.u64 t, %1; cvt.u32.u64 %0, t; }" : "=r"(a) : "l"(p));
    return a;
}
#define CP16(sm, gp) \
    asm volatile("cp.async.cg.shared.global [%0], [%1], 16;" :: "r"(sm), "l"(gp) : "memory")
#define CP_COMMIT() asm volatile("cp.async.commit_group;" ::: "memory")
#define CP_WAIT(n)  asm volatile("cp.async.wait_group %0;" :: "n"(n) : "memory")

#define LDSM_X4(r, addr)                                                        \
    asm volatile("ldmatrix.sync.aligned.m8n8.x4.shared.b16 {%0,%1,%2,%3}, [%4];" \
        : "=r"((r)[0]), "=r"((r)[1]), "=r"((r)[2]), "=r"((r)[3]) : "r"(addr))

#define MMA16816(c, a, b0, b1)                                                  \
    asm volatile("mma.sync.aligned.m16n8k16.row.col.f32.f16.f16.f32 "           \
        "{%0,%1,%2,%3}, {%4,%5,%6,%7}, {%8,%9}, {%0,%1,%2,%3};"                 \
        : "+f"((c)[0]), "+f"((c)[1]), "+f"((c)[2]), "+f"((c)[3])                \
        : "r"((a)[0]), "r"((a)[1]), "r"((a)[2]), "r"((a)[3]), "r"(b0), "r"(b1))

__device__ __forceinline__ float sigf(float x) { return 1.f / (1.f + __expf(-x)); }
__device__ __forceinline__ float tanhf_(float x) {
    float t = __expf(-2.f * x);
    return (1.f - t) * (1.f / (1.f + t));
}

// ---------------- pack kernels ---------------------------------------------
__global__ void __launch_bounds__(256) pack_A(const float* __restrict__ x,
                                              const float* __restrict__ h) {
    int i = blockIdx.x * 256 + threadIdx.x;
    int b = i >> 8;
    int k = (i & 255) << 2;
    float4 vx = *reinterpret_cast<const float4*>(x + (size_t)b * IN_DIM + k);
    float4 vh = *reinterpret_cast<const float4*>(h + (size_t)b * H_DIM + k);
    __half2* dx = reinterpret_cast<__half2*>(g_A + (size_t)b * KTOT + k);
    dx[0] = __floats2half2_rn(vx.x, vx.y);
    dx[1] = __floats2half2_rn(vx.z, vx.w);
    __half2* dh = reinterpret_cast<__half2*>(g_A + (size_t)b * KTOT + IN_DIM + k);
    dh[0] = __floats2half2_rn(vh.x, vh.y);
    dh[1] = __floats2half2_rn(vh.z, vh.w);
}

__global__ void __launch_bounds__(256) pack_W(
    const float* __restrict__ Wix, const float* __restrict__ Wfx,
    const float* __restrict__ Wgx, const float* __restrict__ Wox,
    const float* __restrict__ Wih, const float* __restrict__ Wfh,
    const float* __restrict__ Wgh, const float* __restrict__ Woh) {
    int i = blockIdx.x * 256 + threadIdx.x;
    int n = i >> 9;
    int k = (i & 511) << 2;
    int r = n >> 2;
    int g = n & 3;
    const float* src;
    if (k < IN_DIM) {
        const float* w = (g == 0) ? Wix : (g == 1) ? Wfx : (g == 2) ? Wgx : Wox;
        src = w + (size_t)r * IN_DIM + k;
    } else {
        const float* w = (g == 0) ? Wih : (g == 1) ? Wfh : (g == 2) ? Wgh : Woh;
        src = w + (size_t)r * H_DIM + (k - IN_DIM);
    }
    float4 v = *reinterpret_cast<const float4*>(src);
    __half2* d = reinterpret_cast<__half2*>(g_W + (size_t)n * KTOT + k);
    d[0] = __floats2half2_rn(v.x, v.y);
    d[1] = __floats2half2_rn(v.z, v.w);
}

__global__ void __launch_bounds__(256) pack_bias(
    const float* __restrict__ bi, const float* __restrict__ bf,
    const float* __restrict__ bg, const float* __restrict__ bo) {
    int i = blockIdx.x * 256 + threadIdx.x;
    int r = i >> 2;
    int g = i & 3;
    const float* b = (g == 0) ? bi : (g == 1) ? bf : (g == 2) ? bg : bo;
    g_bias[i] = b[r];
}

// ---------------- GEMM + fused LSTM epilogue --------------------------------
// R2 structure (CTA 256thr, tile 128x128, warp 32x64, 2 CTAs/SM) with a
// 5-stage ring and TWO K=32 slots consumed per barrier: 32 syncs instead
// of 64, 2 stages prefetching during each 2-slot compute phase.
static constexpr int STAGES   = 5;
static constexpr int ROW_B    = 80;       // 32 halves + 8 pad
static constexpr int A_BYTES  = 128 * ROW_B;          // 10240
static constexpr int STAGE_B  = 2 * A_BYTES;          // 20480
static constexpr int SMEM_DYN = STAGES * STAGE_B;     // 102400
static constexpr int KITERS   = KTOT / 32;            // 64 K-slots
static constexpr int PAIRS    = KITERS / 2;           // 32 barrier phases

__global__ void __launch_bounds__(256, 2) lstm_gemm(
    const float* __restrict__ c_prev, float* __restrict__ out) {
    extern __shared__ __align__(128) char smem[];
    const uint32_t sbase = smem_u32(smem);

    const int tid = threadIdx.x;
    const int l   = tid & 31;
    const int wid = tid >> 5;
    const int wm  = wid >> 1;          // 0..3 : 32-row slice
    const int wn  = wid & 1;           // 0..1 : 64-packed-col slice
    const int bn  = blockIdx.x;        // 0..31
    const int bm  = blockIdx.y;        // 0..63

    // ---- global load mapping: thread -> (row = tid>>2, 16B chunk = tid&3)
    const int grow = tid >> 2;
    const int gch  = tid & 3;
    const __half* gA0 = g_A + (size_t)(bm * 128 + grow) * KTOT + gch * 8;
    const __half* gB0 = g_W + (size_t)(bn * 128 + grow) * KTOT + gch * 8;
    const uint32_t smA0 = sbase + grow * ROW_B + gch * 16;
    const uint32_t smB0 = smA0 + A_BYTES;

    // ---- ldmatrix lane address bases (stage 0)
    const uint32_t laA = sbase + (uint32_t)(wm * 32 + (l & 7) + 8 * ((l >> 3) & 1)) * ROW_B
                       + (uint32_t)(l >> 4) * 16;
    const uint32_t laB = sbase + A_BYTES
                       + (uint32_t)(wn * 64 + (l & 7) + 8 * (l >> 4)) * ROW_B
                       + (uint32_t)((l >> 3) & 1) * 16;

    float acc[2][8][4];
#pragma unroll
    for (int mb = 0; mb < 2; mb++)
#pragma unroll
        for (int nb = 0; nb < 8; nb++)
#pragma unroll
            for (int q = 0; q < 4; q++) acc[mb][nb][q] = 0.f;

#define ISSUE_STAGE(kt) do {                                                    \
    const int _slot = (kt) % STAGES;                                            \
    const __half* ga = gA0 + (kt) * 32;                                         \
    const __half* gb = gB0 + (kt) * 32;                                         \
    uint32_t sa  = smA0 + (uint32_t)_slot * STAGE_B;                            \
    uint32_t sb2 = smB0 + (uint32_t)_slot * STAGE_B;                            \
    CP16(sa,                 ga);                                               \
    CP16(sa + 64 * ROW_B,    ga + (size_t)64 * KTOT);                           \
    CP16(sb2,                gb);                                               \
    CP16(sb2 + 64 * ROW_B,   gb + (size_t)64 * KTOT);                           \
} while (0)

    // ---- prologue: fill 3 stages
    ISSUE_STAGE(0); CP_COMMIT();
    ISSUE_STAGE(1); CP_COMMIT();
    ISSUE_STAGE(2); CP_COMMIT();

    // ---- main loop: 32 phases, each consumes slots j, j+1
    for (int it = 0; it < PAIRS; it++) {
        const int j = 2 * it;
        if (it == PAIRS - 1) { CP_WAIT(0); } else { CP_WAIT(1); }
        __syncthreads();

        int kt0 = j + 3, kt1 = j + 4;
        if (kt0 < KITERS) { ISSUE_STAGE(kt0); CP_COMMIT(); }
        if (kt1 < KITERS) { ISSUE_STAGE(kt1); CP_COMMIT(); }

#pragma unroll
        for (int half = 0; half < 2; half++) {
            const uint32_t so = (uint32_t)((j + half) % STAGES) * STAGE_B;
#pragma unroll
            for (int ks = 0; ks < 2; ks++) {
                uint32_t af[2][4], bf[4][4];
                uint32_t ao = laA + so + ks * 32;
                uint32_t bo = laB + so + ks * 32;
#pragma unroll
                for (int mb = 0; mb < 2; mb++) LDSM_X4(af[mb], ao + mb * 16 * ROW_B);
#pragma unroll
                for (int p = 0; p < 4; p++) LDSM_X4(bf[p], bo + p * 16 * ROW_B);
#pragma unroll
                for (int mb = 0; mb < 2; mb++)
#pragma unroll
                    for (int p = 0; p < 4; p++) {
                        MMA16816(acc[mb][2 * p],     af[mb], bf[p][0], bf[p][1]);
                        MMA16816(acc[mb][2 * p + 1], af[mb], bf[p][2], bf[p][3]);
                    }
            }
        }
    }
    __syncthreads();   // ring smem now free for epilogue staging

    // ---- stage c_prev tile [128 x 32] into smem (coalesced), stride 34
    float* sh_c = reinterpret_cast<float*>(smem);
    float* sh_h = sh_c + 128 * 34;
    float* sh_n = sh_h + 128 * 34;
#pragma unroll
    for (int it = 0; it < 8; it++) {
        int idx = it * 256 + tid;            // 0..2047 float2 slots
        int row = idx >> 4, seg = idx & 15;
        float2 v = *reinterpret_cast<const float2*>(
            c_prev + (size_t)(bm * 128 + row) * H_DIM + bn * 32 + seg * 2);
        *reinterpret_cast<float2*>(sh_c + row * 34 + seg * 2) = v;
    }
    __syncthreads();

    // ---- fused LSTM epilogue (gate-interleaved cols i,f,g,o)
    const int q = l & 3;
#pragma unroll
    for (int mb = 0; mb < 2; mb++) {
#pragma unroll
        for (int nb = 0; nb < 8; nb++) {
            int colbase = bn * 128 + wn * 64 + nb * 8;
            float2 bb = *reinterpret_cast<const float2*>(g_bias + colbase + 2 * q);
            float a0 = acc[mb][nb][0] + bb.x;
            float a1 = acc[mb][nb][1] + bb.y;
            float a2 = acc[mb][nb][2] + bb.x;
            float a3 = acc[mb][nb][3] + bb.y;
            float r0 = __shfl_xor_sync(0xFFFFFFFFu, a0, 1);
            float r1 = __shfl_xor_sync(0xFFFFFFFFu, a1, 1);
            float r2 = __shfl_xor_sync(0xFFFFFFFFu, a2, 1);
            float r3 = __shfl_xor_sync(0xFFFFFFFFu, a3, 1);
            bool ev = (l & 1) == 0;
            float zi = ev ? a0 : r2;
            float zf = ev ? a1 : r3;
            float zg = ev ? r0 : a2;
            float zo = ev ? r1 : a3;
            int rl   = wm * 32 + mb * 16 + ((l >> 2) & 7) + (l & 1) * 8;
            int hcol = wn * 16 + nb * 2 + ((l >> 1) & 1);
            float cp = sh_c[rl * 34 + hcol];
            float gi = sigf(zi), gf = sigf(zf);
            float gg = tanhf_(zg), go = sigf(zo);
            float cn = gf * cp + gi * gg;
            float hn = go * tanhf_(cn);
            sh_h[rl * 34 + hcol] = hn;
            sh_n[rl * 34 + hcol] = cn;
        }
    }
    __syncthreads();

    // ---- coalesced stores
    float* oh = out + (size_t)(bm * 128) * H_DIM + bn * 32;
    float* oc = oh + (size_t)BH;
#pragma unroll
    for (int it = 0; it < 8; it++) {
        int idx = it * 256 + tid;
        int row = idx >> 4, seg = idx & 15;
        float2 vh = *reinterpret_cast<const float2*>(sh_h + row * 34 + seg * 2);
        float2 vc = *reinterpret_cast<const float2*>(sh_n + row * 34 + seg * 2);
        *reinterpret_cast<float2*>(oh + (size_t)row * H_DIM + seg * 2) = vh;
        *reinterpret_cast<float2*>(oc + (size_t)row * H_DIM + seg * 2) = vc;
    }
}

// ---------------- host side -------------------------------------------------
extern "C" void kernel_launch(void* const* d_in, const int* in_sizes, int n_in,
                              void* d_out, int out_size) {
    const float* x   = (const float*)d_in[0];
    const float* h   = (const float*)d_in[1];
    const float* cp  = (const float*)d_in[2];
    const float* Wfx = (const float*)d_in[3];
    const float* bf  = (const float*)d_in[4];
    const float* Wfh = (const float*)d_in[5];
    const float* Wix = (const float*)d_in[6];
    const float* bi  = (const float*)d_in[7];
    const float* Wih = (const float*)d_in[8];
    const float* Wgx = (const float*)d_in[9];
    const float* bg  = (const float*)d_in[10];
    const float* Wgh = (const float*)d_in[11];
    const float* Wox = (const float*)d_in[12];
    const float* bo  = (const float*)d_in[13];
    const float* Woh = (const float*)d_in[14];

    pack_A<<<8192, 256>>>(x, h);
    pack_W<<<8192, 256>>>(Wix, Wfx, Wgx, Wox, Wih, Wfh, Wgh, Woh);
    pack_bias<<<16, 256>>>(bi, bf, bg, bo);

    static bool attr_set = false;
    if (!attr_set) {
        cudaFuncSetAttribute(lstm_gemm, cudaFuncAttributeMaxDynamicSharedMemorySize, SMEM_DYN);
        attr_set = true;
    }
    lstm_gemm<<<dim3(N4H / 128, B_DIM / 128), 256, SMEM_DYN>>>(cp, (float*)d_out);
}

// round 16
// speedup vs baseline: 1.3651x; 1.0950x over previous
#include <cuda_runtime.h>
#include <cuda_fp16.h>
#include <cstdint>

#define B_DIM  8192
#define IN_DIM 1024
#define H_DIM  1024
#define KTOT   2048
#define N4H    4096
#define BH     (B_DIM * H_DIM)

// ---------------- device scratch (static globals: allocation-free) ----------
__device__ __align__(1024) __half g_A[(size_t)B_DIM * KTOT];   // [8192,2048] fp16  [x | h]
__device__ __align__(1024) __half g_W[(size_t)N4H * KTOT];     // [4096,2048] fp16, row = 4*h+gate
__device__ __align__(1024) float  g_bias[N4H];                 // interleaved 4*h+gate (i,f,g,o)

// ---------------- PTX helpers ----------------------------------------------
__device__ __forceinline__ uint32_t smem_u32(const void* p) {
    uint32_t a;
    asm("{ .reg .u64 t; cvta.to.shared.u64 t, %1; cvt.u32.u64 %0, t; }" : "=r"(a) : "l"(p));
    return a;
}
#define CP16(sm, gp) \
    asm volatile("cp.async.cg.shared.global [%0], [%1], 16;" :: "r"(sm), "l"(gp) : "memory")
#define CP_COMMIT() asm volatile("cp.async.commit_group;" ::: "memory")
#define CP_WAIT(n)  asm volatile("cp.async.wait_group %0;" :: "n"(n) : "memory")

#define LDSM_X4(r, addr)                                                        \
    asm volatile("ldmatrix.sync.aligned.m8n8.x4.shared.b16 {%0,%1,%2,%3}, [%4];" \
        : "=r"((r)[0]), "=r"((r)[1]), "=r"((r)[2]), "=r"((r)[3]) : "r"(addr))

#define MMA16816(c, a, b0, b1)                                                  \
    asm volatile("mma.sync.aligned.m16n8k16.row.col.f32.f16.f16.f32 "           \
        "{%0,%1,%2,%3}, {%4,%5,%6,%7}, {%8,%9}, {%0,%1,%2,%3};"                 \
        : "+f"((c)[0]), "+f"((c)[1]), "+f"((c)[2]), "+f"((c)[3])                \
        : "r"((a)[0]), "r"((a)[1]), "r"((a)[2]), "r"((a)[3]), "r"(b0), "r"(b1))

__device__ __forceinline__ float sigf(float x) { return 1.f / (1.f + __expf(-x)); }
__device__ __forceinline__ float tanhf_(float x) {
    float t = __expf(-2.f * x);
    return (1.f - t) * (1.f / (1.f + t));
}

// ---------------- pack kernels ---------------------------------------------
__global__ void __launch_bounds__(256) pack_A(const float* __restrict__ x,
                                              const float* __restrict__ h) {
    int i = blockIdx.x * 256 + threadIdx.x;
    int b = i >> 8;
    int k = (i & 255) << 2;
    float4 vx = *reinterpret_cast<const float4*>(x + (size_t)b * IN_DIM + k);
    float4 vh = *reinterpret_cast<const float4*>(h + (size_t)b * H_DIM + k);
    __half2* dx = reinterpret_cast<__half2*>(g_A + (size_t)b * KTOT + k);
    dx[0] = __floats2half2_rn(vx.x, vx.y);
    dx[1] = __floats2half2_rn(vx.z, vx.w);
    __half2* dh = reinterpret_cast<__half2*>(g_A + (size_t)b * KTOT + IN_DIM + k);
    dh[0] = __floats2half2_rn(vh.x, vh.y);
    dh[1] = __floats2half2_rn(vh.z, vh.w);
}

__global__ void __launch_bounds__(256) pack_W(
    const float* __restrict__ Wix, const float* __restrict__ Wfx,
    const float* __restrict__ Wgx, const float* __restrict__ Wox,
    const float* __restrict__ Wih, const float* __restrict__ Wfh,
    const float* __restrict__ Wgh, const float* __restrict__ Woh) {
    int i = blockIdx.x * 256 + threadIdx.x;
    int n = i >> 9;
    int k = (i & 511) << 2;
    int r = n >> 2;
    int g = n & 3;
    const float* src;
    if (k < IN_DIM) {
        const float* w = (g == 0) ? Wix : (g == 1) ? Wfx : (g == 2) ? Wgx : Wox;
        src = w + (size_t)r * IN_DIM + k;
    } else {
        const float* w = (g == 0) ? Wih : (g == 1) ? Wfh : (g == 2) ? Wgh : Woh;
        src = w + (size_t)r * H_DIM + (k - IN_DIM);
    }
    float4 v = *reinterpret_cast<const float4*>(src);
    __half2* d = reinterpret_cast<__half2*>(g_W + (size_t)n * KTOT + k);
    d[0] = __floats2half2_rn(v.x, v.y);
    d[1] = __floats2half2_rn(v.z, v.w);
}

__global__ void __launch_bounds__(256) pack_bias(
    const float* __restrict__ bi, const float* __restrict__ bf,
    const float* __restrict__ bg, const float* __restrict__ bo) {
    int i = blockIdx.x * 256 + threadIdx.x;
    int r = i >> 2;
    int g = i & 3;
    const float* b = (g == 0) ? bi : (g == 1) ? bf : (g == 2) ? bg : bo;
    g_bias[i] = b[r];
}

// ---------------- GEMM + fused LSTM epilogue --------------------------------
// R2 structure exactly (CTA 256thr, tile 128x128, warp 32x64, 2 CTAs/SM),
// with: 5-stage ring + CP_WAIT(3) (consumed slot is oldest of 4 in flight,
// wait never blocks) and ISSUE_STAGE moved AFTER compute (LDSM starts
// immediately post-barrier). One K=32 slot per barrier, 64 barriers.
static constexpr int STAGES   = 5;
static constexpr int ROW_B    = 80;       // 32 halves + 8 pad
static constexpr int A_BYTES  = 128 * ROW_B;          // 10240
static constexpr int STAGE_B  = 2 * A_BYTES;          // 20480
static constexpr int SMEM_DYN = STAGES * STAGE_B;     // 102400
static constexpr int KITERS   = KTOT / 32;            // 64

__global__ void __launch_bounds__(256, 2) lstm_gemm(
    const float* __restrict__ c_prev, float* __restrict__ out) {
    extern __shared__ __align__(128) char smem[];
    const uint32_t sbase = smem_u32(smem);

    const int tid = threadIdx.x;
    const int l   = tid & 31;
    const int wid = tid >> 5;
    const int wm  = wid >> 1;          // 0..3 : 32-row slice
    const int wn  = wid & 1;           // 0..1 : 64-packed-col slice
    const int bn  = blockIdx.x;        // 0..31
    const int bm  = blockIdx.y;        // 0..63

    // ---- global load mapping: thread -> (row = tid>>2, 16B chunk = tid&3)
    const int grow = tid >> 2;
    const int gch  = tid & 3;
    const __half* gA0 = g_A + (size_t)(bm * 128 + grow) * KTOT + gch * 8;
    const __half* gB0 = g_W + (size_t)(bn * 128 + grow) * KTOT + gch * 8;
    const uint32_t smA0 = sbase + grow * ROW_B + gch * 16;
    const uint32_t smB0 = smA0 + A_BYTES;

    // ---- ldmatrix lane address bases (stage 0)
    const uint32_t laA = sbase + (uint32_t)(wm * 32 + (l & 7) + 8 * ((l >> 3) & 1)) * ROW_B
                       + (uint32_t)(l >> 4) * 16;
    const uint32_t laB = sbase + A_BYTES
                       + (uint32_t)(wn * 64 + (l & 7) + 8 * (l >> 4)) * ROW_B
                       + (uint32_t)((l >> 3) & 1) * 16;

    float acc[2][8][4];
#pragma unroll
    for (int mb = 0; mb < 2; mb++)
#pragma unroll
        for (int nb = 0; nb < 8; nb++)
#pragma unroll
            for (int q = 0; q < 4; q++) acc[mb][nb][q] = 0.f;

#define ISSUE_STAGE(kt) do {                                                    \
    const int _slot = (kt) % STAGES;                                            \
    const __half* ga = gA0 + (kt) * 32;                                         \
    const __half* gb = gB0 + (kt) * 32;                                         \
    uint32_t sa  = smA0 + (uint32_t)_slot * STAGE_B;                            \
    uint32_t sb2 = smB0 + (uint32_t)_slot * STAGE_B;                            \
    CP16(sa,               ga);                                                 \
    CP16(sa + 64 * ROW_B,  ga + (size_t)64 * KTOT);                             \
    CP16(sb2,              gb);                                                 \
    CP16(sb2 + 64 * ROW_B, gb + (size_t)64 * KTOT);                             \
} while (0)

    // ---- prologue: fill 4 stages
    ISSUE_STAGE(0); CP_COMMIT();
    ISSUE_STAGE(1); CP_COMMIT();
    ISSUE_STAGE(2); CP_COMMIT();
    ISSUE_STAGE(3); CP_COMMIT();

    // ---- main loop: one K=32 slot per barrier; issue AFTER compute
    for (int i = 0; i < KITERS; i++) {
        if (i >= KITERS - 4) { CP_WAIT(0); } else { CP_WAIT(3); }
        __syncthreads();

        const uint32_t so = (uint32_t)(i % STAGES) * STAGE_B;
#pragma unroll
        for (int ks = 0; ks < 2; ks++) {
            uint32_t af[2][4], bf[4][4];
            uint32_t ao = laA + so + ks * 32;
            uint32_t bo = laB + so + ks * 32;
#pragma unroll
            for (int mb = 0; mb < 2; mb++) LDSM_X4(af[mb], ao + mb * 16 * ROW_B);
#pragma unroll
            for (int p = 0; p < 4; p++) LDSM_X4(bf[p], bo + p * 16 * ROW_B);
#pragma unroll
            for (int mb = 0; mb < 2; mb++)
#pragma unroll
                for (int p = 0; p < 4; p++) {
                    MMA16816(acc[mb][2 * p],     af[mb], bf[p][0], bf[p][1]);
                    MMA16816(acc[mb][2 * p + 1], af[mb], bf[p][2], bf[p][3]);
                }
        }

        int kt = i + 4;                       // overwrites slot (i+4)%5 = (i-1)%5,
        if (kt < KITERS) {                    // consumed last iter; safe post-barrier
            ISSUE_STAGE(kt);
            CP_COMMIT();
        }
    }
    __syncthreads();   // ring smem now free for epilogue staging

    // ---- stage c_prev tile [128 x 32] into smem (coalesced), stride 34
    float* sh_c = reinterpret_cast<float*>(smem);
    float* sh_h = sh_c + 128 * 34;
    float* sh_n = sh_h + 128 * 34;
#pragma unroll
    for (int it = 0; it < 8; it++) {
        int idx = it * 256 + tid;            // 0..2047 float2 slots
        int row = idx >> 4, seg = idx & 15;
        float2 v = *reinterpret_cast<const float2*>(
            c_prev + (size_t)(bm * 128 + row) * H_DIM + bn * 32 + seg * 2);
        *reinterpret_cast<float2*>(sh_c + row * 34 + seg * 2) = v;
    }
    __syncthreads();

    // ---- fused LSTM epilogue (gate-interleaved cols i,f,g,o)
    const int q = l & 3;
#pragma unroll
    for (int mb = 0; mb < 2; mb++) {
#pragma unroll
        for (int nb = 0; nb < 8; nb++) {
            int colbase = bn * 128 + wn * 64 + nb * 8;
            float2 bb = *reinterpret_cast<const float2*>(g_bias + colbase + 2 * q);
            float a0 = acc[mb][nb][0] + bb.x;
            float a1 = acc[mb][nb][1] + bb.y;
            float a2 = acc[mb][nb][2] + bb.x;
            float a3 = acc[mb][nb][3] + bb.y;
            float r0 = __shfl_xor_sync(0xFFFFFFFFu, a0, 1);
            float r1 = __shfl_xor_sync(0xFFFFFFFFu, a1, 1);
            float r2 = __shfl_xor_sync(0xFFFFFFFFu, a2, 1);
            float r3 = __shfl_xor_sync(0xFFFFFFFFu, a3, 1);
            bool ev = (l & 1) == 0;
            float zi = ev ? a0 : r2;
            float zf = ev ? a1 : r3;
            float zg = ev ? r0 : a2;
            float zo = ev ? r1 : a3;
            int rl   = wm * 32 + mb * 16 + ((l >> 2) & 7) + (l & 1) * 8;
            int hcol = wn * 16 + nb * 2 + ((l >> 1) & 1);
            float cp = sh_c[rl * 34 + hcol];
            float gi = sigf(zi), gf = sigf(zf);
            float gg = tanhf_(zg), go = sigf(zo);
            float cn = gf * cp + gi * gg;
            float hn = go * tanhf_(cn);
            sh_h[rl * 34 + hcol] = hn;
            sh_n[rl * 34 + hcol] = cn;
        }
    }
    __syncthreads();

    // ---- coalesced stores
    float* oh = out + (size_t)(bm * 128) * H_DIM + bn * 32;
    float* oc = oh + (size_t)BH;
#pragma unroll
    for (int it = 0; it < 8; it++) {
        int idx = it * 256 + tid;
        int row = idx >> 4, seg = idx & 15;
        float2 vh = *reinterpret_cast<const float2*>(sh_h + row * 34 + seg * 2);
        float2 vc = *reinterpret_cast<const float2*>(sh_n + row * 34 + seg * 2);
        *reinterpret_cast<float2*>(oh + (size_t)row * H_DIM + seg * 2) = vh;
        *reinterpret_cast<float2*>(oc + (size_t)row * H_DIM + seg * 2) = vc;
    }
}

// ---------------- host side -------------------------------------------------
extern "C" void kernel_launch(void* const* d_in, const int* in_sizes, int n_in,
                              void* d_out, int out_size) {
    const float* x   = (const float*)d_in[0];
    const float* h   = (const float*)d_in[1];
    const float* cp  = (const float*)d_in[2];
    const float* Wfx = (const float*)d_in[3];
    const float* bf  = (const float*)d_in[4];
    const float* Wfh = (const float*)d_in[5];
    const float* Wix = (const float*)d_in[6];
    const float* bi  = (const float*)d_in[7];
    const float* Wih = (const float*)d_in[8];
    const float* Wgx = (const float*)d_in[9];
    const float* bg  = (const float*)d_in[10];
    const float* Wgh = (const float*)d_in[11];
    const float* Wox = (const float*)d_in[12];
    const float* bo  = (const float*)d_in[13];
    const float* Woh = (const float*)d_in[14];

    pack_A<<<8192, 256>>>(x, h);
    pack_W<<<8192, 256>>>(Wix, Wfx, Wgx, Wox, Wih, Wfh, Wgh, Woh);
    pack_bias<<<16, 256>>>(bi, bf, bg, bo);

    static bool attr_set = false;
    if (!attr_set) {
        cudaFuncSetAttribute(lstm_gemm, cudaFuncAttributeMaxDynamicSharedMemorySize, SMEM_DYN);
        attr_set = true;
    }
    lstm_gemm<<<dim3(N4H / 128, B_DIM / 128), 256, SMEM_DYN>>>(cp, (float*)d_out);
}